// round 1
// baseline (speedup 1.0000x reference)
#include <cuda_runtime.h>
#include <math.h>

#define E_DIM 256
#define F_DIM 768
#define B_DIM 256
#define TI    64
#define BSP   260            // padded Bs row (floats), multiple of 4 for LDS.128
#define ATT_SCALE 0.0625f    // 1/sqrt(256)

#define SMEM_FLOATS (3*TI*E_DIM + 16*BSP + E_DIM + TI)
#define SMEM_BYTES  (SMEM_FLOATS * (int)sizeof(float))

// ---------------- device scratch (no runtime allocation allowed) -------------
__device__ float g_enc1[B_DIM*E_DIM];
__device__ float g_enc2[B_DIM*E_DIM];
__device__ float g_affa[B_DIM*E_DIM];
__device__ float g_affv[B_DIM*E_DIM];
__device__ float g_Xa  [E_DIM*E_DIM];
__device__ float g_Xv  [E_DIM*E_DIM];

// ---------------- small precompute GEMM:  C[256,256] = A[256,K] @ W[256,K]^T (+bias)
__device__ __forceinline__ void small_gemm(const float* __restrict__ A,
                                           const float* __restrict__ W,
                                           const float* __restrict__ bias,
                                           float* __restrict__ C, int K)
{
    __shared__ float As[64][17];
    __shared__ float Ws[64][17];
    const int i0 = blockIdx.x * 64, j0 = blockIdx.y * 64;
    const int tid = threadIdx.x;
    const int tx = tid & 15, ty = tid >> 4;
    const int lr = tid >> 2, lk = (tid & 3) * 4;
    float acc[4][4] = {};
    for (int k0 = 0; k0 < K; k0 += 16) {
        float4 av = *(const float4*)(A + (size_t)(i0 + lr) * K + k0 + lk);
        float4 wv = *(const float4*)(W + (size_t)(j0 + lr) * K + k0 + lk);
        __syncthreads();
        As[lr][lk] = av.x; As[lr][lk+1] = av.y; As[lr][lk+2] = av.z; As[lr][lk+3] = av.w;
        Ws[lr][lk] = wv.x; Ws[lr][lk+1] = wv.y; Ws[lr][lk+2] = wv.z; Ws[lr][lk+3] = wv.w;
        __syncthreads();
        #pragma unroll
        for (int kk = 0; kk < 16; kk++) {
            float a[4], bb[4];
            #pragma unroll
            for (int u = 0; u < 4; u++) a[u]  = As[ty*4+u][kk];
            #pragma unroll
            for (int v = 0; v < 4; v++) bb[v] = Ws[tx*4+v][kk];
            #pragma unroll
            for (int u = 0; u < 4; u++)
                #pragma unroll
                for (int v = 0; v < 4; v++)
                    acc[u][v] = fmaf(a[u], bb[v], acc[u][v]);
        }
    }
    #pragma unroll
    for (int u = 0; u < 4; u++)
        #pragma unroll
        for (int v = 0; v < 4; v++) {
            int j = j0 + tx*4 + v;
            float x = acc[u][v];
            if (bias) x += bias[j];
            C[(size_t)(i0 + ty*4 + u) * E_DIM + j] = x;
        }
}

__global__ void pre_enc_kernel(const float* __restrict__ f1, const float* __restrict__ f2,
                               const float* __restrict__ w1, const float* __restrict__ b1,
                               const float* __restrict__ w2, const float* __restrict__ b2)
{
    if (blockIdx.z == 0) small_gemm(f1, w1, b1, g_enc1, F_DIM);
    else                 small_gemm(f2, w2, b2, g_enc2, F_DIM);
}

__global__ void pre_aff_kernel(const float* __restrict__ affa, const float* __restrict__ affv,
                               const float* __restrict__ wa,   const float* __restrict__ wv)
{
    int z = blockIdx.z;
    const float* A = (z == 0 || z == 2) ? g_enc1 : g_enc2;
    const float* W = (z == 0) ? affa : (z == 1) ? affv : (z == 2) ? wa : wv;
    float*       C = (z == 0) ? g_affa : (z == 1) ? g_affv : (z == 2) ? g_Xa : g_Xv;
    small_gemm(A, W, nullptr, C, E_DIM);
}

// ---------------- main fused kernel ------------------------------------------
// GEMM mainloop: acc[8][8] += A_s[64,256] @ W[256, ldw-strided]^T
// A_s in smem [row i][k] (row len E_DIM); W streamed from global through Bs
// (stored transposed [k][j], padded) with register prefetch.
__device__ __forceinline__ void gemm_main(const float* __restrict__ Wg, int ldw,
                                          const float* As, float* Bs,
                                          float acc[8][8],
                                          int tm, int tn, int lj, int lk)
{
    float4 pre[4];
    #pragma unroll
    for (int r = 0; r < 4; r++)
        pre[r] = *(const float4*)(Wg + (size_t)(lj + 64*r) * ldw + lk);

    for (int k0 = 0; k0 < E_DIM; k0 += 16) {
        __syncthreads();                       // previous tile fully consumed
        #pragma unroll
        for (int r = 0; r < 4; r++) {          // transpose-store, conflict-light
            float* dst = Bs + lk * BSP + (lj + 64*r);
            dst[0]       = pre[r].x;
            dst[BSP]     = pre[r].y;
            dst[2*BSP]   = pre[r].z;
            dst[3*BSP]   = pre[r].w;
        }
        __syncthreads();
        if (k0 + 16 < E_DIM) {
            #pragma unroll
            for (int r = 0; r < 4; r++)
                pre[r] = *(const float4*)(Wg + (size_t)(lj + 64*r) * ldw + (k0 + 16) + lk);
        }
        #pragma unroll
        for (int kk = 0; kk < 16; kk += 4) {
            float4 a4[8];
            #pragma unroll
            for (int rr = 0; rr < 8; rr++)
                a4[rr] = *(const float4*)(As + (tm*8 + rr) * E_DIM + (k0 + kk));
            #pragma unroll
            for (int q = 0; q < 4; q++) {
                float bv[8];
                *(float4*)(bv)     = *(const float4*)(Bs + (kk + q) * BSP + tn*8);
                *(float4*)(bv + 4) = *(const float4*)(Bs + (kk + q) * BSP + tn*8 + 4);
                #pragma unroll
                for (int rr = 0; rr < 8; rr++) {
                    float av = ((const float*)&a4[rr])[q];
                    #pragma unroll
                    for (int cc = 0; cc < 8; cc++)
                        acc[rr][cc] = fmaf(av, bv[cc], acc[rr][cc]);
                }
            }
        }
    }
}

__global__ void __launch_bounds__(256, 1)
fused_kernel(const float* __restrict__ wca, const float* __restrict__ wcv,
             const float* __restrict__ wha, const float* __restrict__ whv,
             const float* __restrict__ fc1w, const float* __restrict__ fc1b,
             const float* __restrict__ fc2w, const float* __restrict__ fc2b,
             float* __restrict__ out)
{
    extern __shared__ float sm[];
    float* A_buf = sm;                         // [64][256]  A operand / attn_enc
    float* O_buf = A_buf + TI*E_DIM;           // [64][256]  H
    float* h_buf = O_buf + TI*E_DIM;           // [64][256]  partial h (branch a)
    float* Bs    = h_buf + TI*E_DIM;           // [16][BSP]  W staging
    float* af    = Bs + 16*BSP;                // [256] aff row
    float* e1s   = af + E_DIM;                 // [64]  enc row slice

    const int tid = threadIdx.x;
    const int b   = blockIdx.y;
    const int i0  = blockIdx.x * TI;
    const int tm  = tid >> 5, tn = tid & 31;   // 8x32 thread grid, 8x8 micro tiles
    const int lj  = tid >> 2, lk = (tid & 3) * 4;

    for (int br = 0; br < 2; br++) {
        const float* genc = br ? g_enc2 : g_enc1;
        const float* gaff = br ? g_affv : g_affa;
        const float* gX   = br ? g_Xv   : g_Xa;
        const float* Wc   = br ? wcv : wca;
        const float* Wh   = br ? whv : wha;

        // ---- stage aff row + enc slice ----
        __syncthreads();
        af[tid] = gaff[b * E_DIM + tid];
        if (tid < TI) e1s[tid] = genc[b * E_DIM + i0 + tid];
        __syncthreads();

        // ---- generate attn tile: A_buf[i][k] = tanh(enc[b,i0+i]*aff[b,k]/16) ----
        {
            int gi = tid >> 2;
            int kb = (tid & 3) * 4;
            float ei = e1s[gi] * ATT_SCALE;
            for (int rep = 0; rep < 16; rep++) {
                int k = kb + rep * 16;
                float4 v;
                v.x = tanhf(ei * af[k]);
                v.y = tanhf(ei * af[k+1]);
                v.z = tanhf(ei * af[k+2]);
                v.w = tanhf(ei * af[k+3]);
                *(float4*)(A_buf + gi * E_DIM + k) = v;
            }
        }
        __syncthreads();

        float acc[8][8];

        // ---- GEMM1: O = relu(attn @ Wc^T + X) ----
        #pragma unroll
        for (int rr = 0; rr < 8; rr++)
            #pragma unroll
            for (int cc = 0; cc < 8; cc++) acc[rr][cc] = 0.f;
        gemm_main(Wc, E_DIM, A_buf, Bs, acc, tm, tn, lj, lk);
        #pragma unroll
        for (int rr = 0; rr < 8; rr++) {
            int r = tm*8 + rr;
            const float* xr = gX + (size_t)(i0 + r) * E_DIM + tn*8;
            float4 x0 = *(const float4*)xr;
            float4 x1 = *(const float4*)(xr + 4);
            float4 o0, o1;
            o0.x = fmaxf(acc[rr][0] + x0.x, 0.f);
            o0.y = fmaxf(acc[rr][1] + x0.y, 0.f);
            o0.z = fmaxf(acc[rr][2] + x0.z, 0.f);
            o0.w = fmaxf(acc[rr][3] + x0.w, 0.f);
            o1.x = fmaxf(acc[rr][4] + x1.x, 0.f);
            o1.y = fmaxf(acc[rr][5] + x1.y, 0.f);
            o1.z = fmaxf(acc[rr][6] + x1.z, 0.f);
            o1.w = fmaxf(acc[rr][7] + x1.w, 0.f);
            *(float4*)(O_buf + r * E_DIM + tn*8)     = o0;
            *(float4*)(O_buf + r * E_DIM + tn*8 + 4) = o1;
        }
        __syncthreads();

        // ---- GEMM2: A_buf = O @ Wh^T + enc  (no relu) ----
        #pragma unroll
        for (int rr = 0; rr < 8; rr++)
            #pragma unroll
            for (int cc = 0; cc < 8; cc++) acc[rr][cc] = 0.f;
        gemm_main(Wh, E_DIM, O_buf, Bs, acc, tm, tn, lj, lk);
        #pragma unroll
        for (int rr = 0; rr < 8; rr++) {
            int r = tm*8 + rr;
            const float* er = genc + (size_t)(i0 + r) * E_DIM + tn*8;
            float4 x0 = *(const float4*)er;
            float4 x1 = *(const float4*)(er + 4);
            float4 o0, o1;
            o0.x = acc[rr][0] + x0.x; o0.y = acc[rr][1] + x0.y;
            o0.z = acc[rr][2] + x0.z; o0.w = acc[rr][3] + x0.w;
            o1.x = acc[rr][4] + x1.x; o1.y = acc[rr][5] + x1.y;
            o1.z = acc[rr][6] + x1.z; o1.w = acc[rr][7] + x1.w;
            *(float4*)(A_buf + r * E_DIM + tn*8)     = o0;
            *(float4*)(A_buf + r * E_DIM + tn*8 + 4) = o1;
        }
        __syncthreads();

        // ---- GEMM3: h partial = attn_enc @ fc1_half^T ----
        #pragma unroll
        for (int rr = 0; rr < 8; rr++)
            #pragma unroll
            for (int cc = 0; cc < 8; cc++) acc[rr][cc] = 0.f;
        gemm_main(fc1w + br * E_DIM, 2*E_DIM, A_buf, Bs, acc, tm, tn, lj, lk);

        if (br == 0) {
            #pragma unroll
            for (int rr = 0; rr < 8; rr++) {
                int r = tm*8 + rr;
                float4 o0, o1;
                o0.x = acc[rr][0]; o0.y = acc[rr][1]; o0.z = acc[rr][2]; o0.w = acc[rr][3];
                o1.x = acc[rr][4]; o1.y = acc[rr][5]; o1.z = acc[rr][6]; o1.w = acc[rr][7];
                *(float4*)(h_buf + r * E_DIM + tn*8)     = o0;
                *(float4*)(h_buf + r * E_DIM + tn*8 + 4) = o1;
            }
        } else {
            // ---- final: h = relu(hA + hV + fc1_b); out = h . fc2_w + fc2_b ----
            float4 b0 = *(const float4*)(fc1b + tn*8);
            float4 b1 = *(const float4*)(fc1b + tn*8 + 4);
            float4 w0 = *(const float4*)(fc2w + tn*8);
            float4 w1 = *(const float4*)(fc2w + tn*8 + 4);
            float f2b = fc2b[0];
            #pragma unroll
            for (int rr = 0; rr < 8; rr++) {
                int r = tm*8 + rr;
                float4 h0 = *(const float4*)(h_buf + r * E_DIM + tn*8);
                float4 h1 = *(const float4*)(h_buf + r * E_DIM + tn*8 + 4);
                float ps = 0.f;
                ps += fmaxf(acc[rr][0] + h0.x + b0.x, 0.f) * w0.x;
                ps += fmaxf(acc[rr][1] + h0.y + b0.y, 0.f) * w0.y;
                ps += fmaxf(acc[rr][2] + h0.z + b0.z, 0.f) * w0.z;
                ps += fmaxf(acc[rr][3] + h0.w + b0.w, 0.f) * w0.w;
                ps += fmaxf(acc[rr][4] + h1.x + b1.x, 0.f) * w1.x;
                ps += fmaxf(acc[rr][5] + h1.y + b1.y, 0.f) * w1.y;
                ps += fmaxf(acc[rr][6] + h1.z + b1.z, 0.f) * w1.z;
                ps += fmaxf(acc[rr][7] + h1.w + b1.w, 0.f) * w1.w;
                #pragma unroll
                for (int off = 16; off > 0; off >>= 1)
                    ps += __shfl_xor_sync(0xffffffffu, ps, off);
                if (tn == 0)
                    out[b * E_DIM + i0 + r] = ps + f2b;
            }
        }
    }
}

// ---------------- launch -----------------------------------------------------
extern "C" void kernel_launch(void* const* d_in, const int* in_sizes, int n_in,
                              void* d_out, int out_size)
{
    (void)in_sizes; (void)n_in; (void)out_size;
    const float* f1     = (const float*)d_in[0];
    const float* f2     = (const float*)d_in[1];
    const float* enc1_w = (const float*)d_in[2];
    const float* enc1_b = (const float*)d_in[3];
    const float* enc2_w = (const float*)d_in[4];
    const float* enc2_b = (const float*)d_in[5];
    const float* affa_w = (const float*)d_in[6];
    const float* affv_w = (const float*)d_in[7];
    const float* wa_w   = (const float*)d_in[8];
    const float* wv_w   = (const float*)d_in[9];
    const float* wca_w  = (const float*)d_in[10];
    const float* wcv_w  = (const float*)d_in[11];
    const float* wha_w  = (const float*)d_in[12];
    const float* whv_w  = (const float*)d_in[13];
    const float* fc1_w  = (const float*)d_in[14];
    const float* fc1_b  = (const float*)d_in[15];
    const float* fc2_w  = (const float*)d_in[16];
    const float* fc2_b  = (const float*)d_in[17];
    float* out = (float*)d_out;

    cudaFuncSetAttribute(fused_kernel,
                         cudaFuncAttributeMaxDynamicSharedMemorySize, SMEM_BYTES);

    pre_enc_kernel<<<dim3(4,4,2), 256>>>(f1, f2, enc1_w, enc1_b, enc2_w, enc2_b);
    pre_aff_kernel<<<dim3(4,4,4), 256>>>(affa_w, affv_w, wa_w, wv_w);
    fused_kernel<<<dim3(4, B_DIM), 256, SMEM_BYTES>>>(wca_w, wcv_w, wha_w, whv_w,
                                                      fc1_w, fc1_b, fc2_w, fc2_b, out);
}